// round 1
// baseline (speedup 1.0000x reference)
#include <cuda_runtime.h>

#define T_LEN 2048
#define BSZ 2
#define EMB 1280
#define NH 20
#define HD 64
#define BHEADS (BSZ*NH)          /* 40 */
#define MROWS (T_LEN*BSZ)        /* 4096 */
#define SCALING 0.125f           /* 64^-0.5 */
#define NEG_BIG (-1e30f)

// ---------------- scratch (device globals; no allocation allowed) ----------------
__device__ float g_q[(size_t)BHEADS * T_LEN * HD];
__device__ float g_k[(size_t)BHEADS * T_LEN * HD];
__device__ float g_v[(size_t)BHEADS * T_LEN * HD];
__device__ float g_ctx[(size_t)MROWS * EMB];
__device__ float g_m[BHEADS * T_LEN];
__device__ float g_l[BHEADS * T_LEN];
__device__ int   g_mask_u8;

// ---------------- mask dtype probe ----------------
// If any of the first B*T bytes is nonzero, the mask is 1-byte bools (padding
// bytes live inside that window). If all zero, it must be a wider dtype
// (int32/float) laid out 4 bytes per element -> read as int32 (nonzero test
// also works for float 1.0).
__global__ void probe_mask_kernel(const unsigned char* __restrict__ m)
{
    __shared__ int any;
    if (threadIdx.x == 0) any = 0;
    __syncthreads();
    int acc = 0;
    for (int i = threadIdx.x; i < BSZ * T_LEN; i += blockDim.x) acc |= m[i];
    if (acc) atomicOr(&any, 1);
    __syncthreads();
    if (threadIdx.x == 0) g_mask_u8 = any;
}

__device__ __forceinline__ int mask_at(const void* mp, int idx)
{
    if (g_mask_u8) return ((const unsigned char*)mp)[idx] != 0;
    return ((const int*)mp)[idx] != 0;
}

// ---------------- projection GEMM: out = (X @ W + bias) * scale ----------------
// X: [MROWS, EMB] row-major. W: [EMB, EMB] row-major (k-major rows).
// Tile 128(M) x 64(N), BK=16, 256 threads, 8x4 per-thread micro-tile.
// OUTMODE 0: out[m*EMB + n] (row-major)
// OUTMODE 1: head-major out[((b*NH+h)*T_LEN + t)*HD + d], m = t*BSZ+b, n = h*HD+d
template <int OUTMODE>
__global__ void __launch_bounds__(256)
proj_kernel(const float* __restrict__ X, const float* __restrict__ W,
            const float* __restrict__ bias, float* __restrict__ out, float scale)
{
    __shared__ float As[16][132];   // A transposed: As[kk][m]
    __shared__ float Bs[16][68];    // natural: Bs[kk][n]

    const int tid = threadIdx.x;
    const int tx = tid & 15, ty = tid >> 4;
    const int r0 = ty * 8, c0 = tx * 4;
    const int m0 = blockIdx.x * 128;
    const int n0 = blockIdx.y * 64;

    float acc[8][4];
#pragma unroll
    for (int i = 0; i < 8; i++)
#pragma unroll
        for (int j = 0; j < 4; j++) acc[i][j] = 0.f;

    for (int k0 = 0; k0 < EMB; k0 += 16) {
#pragma unroll
        for (int i = 0; i < 8; i++) {           // A tile 128x16 -> transposed
            int e = tid + i * 256;
            int m = e >> 4, kk = e & 15;
            As[kk][m] = X[(size_t)(m0 + m) * EMB + k0 + kk];
        }
#pragma unroll
        for (int i = 0; i < 4; i++) {           // W tile 16x64 natural
            int e = tid + i * 256;
            int kk = e >> 6, n = e & 63;
            Bs[kk][n] = W[(size_t)(k0 + kk) * EMB + n0 + n];
        }
        __syncthreads();
#pragma unroll
        for (int kk = 0; kk < 16; kk++) {
            float4 a0 = *(const float4*)&As[kk][r0];
            float4 a1 = *(const float4*)&As[kk][r0 + 4];
            float4 bb = *(const float4*)&Bs[kk][c0];
            float av[8] = {a0.x, a0.y, a0.z, a0.w, a1.x, a1.y, a1.z, a1.w};
            float bv[4] = {bb.x, bb.y, bb.z, bb.w};
#pragma unroll
            for (int i = 0; i < 8; i++)
#pragma unroll
                for (int j = 0; j < 4; j++) acc[i][j] += av[i] * bv[j];
        }
        __syncthreads();
    }

#pragma unroll
    for (int i = 0; i < 8; i++) {
        int m = m0 + r0 + i;
        float4 v;
        v.x = (acc[i][0] + bias[n0 + c0 + 0]) * scale;
        v.y = (acc[i][1] + bias[n0 + c0 + 1]) * scale;
        v.z = (acc[i][2] + bias[n0 + c0 + 2]) * scale;
        v.w = (acc[i][3] + bias[n0 + c0 + 3]) * scale;
        if (OUTMODE == 0) {
            *(float4*)&out[(size_t)m * EMB + n0 + c0] = v;
        } else {
            int b = m % BSZ, t = m / BSZ;
            int h = (n0 + c0) >> 6;
            int d = (n0 + c0) & 63;
            *(float4*)&out[(((size_t)(b * NH + h)) * T_LEN + t) * HD + d] = v;
        }
    }
}

// ---------------- pass A: per-row softmax stats (online m, l) ----------------
// grid (T/128, BHEADS); block 256; per-thread 8 q-rows x 4 k-cols
__global__ void __launch_bounds__(256)
attn_stats_kernel(const void* __restrict__ maskp)
{
    extern __shared__ float sm[];
    float (*Qt)[132] = (float (*)[132])sm;                 // [64][132] Qt[d][q]
    float (*Kt)[68]  = (float (*)[68])(sm + 64 * 132);     // [64][68]  Kt[d][k]
    float* mtile     = sm + 64 * 132 + 64 * 68;            // [64]

    const int tid = threadIdx.x;
    const int tx = tid & 15, ty = tid >> 4;
    const int r0 = ty * 8, c0 = tx * 4;
    const int bh = blockIdx.y;
    const int b = bh / NH;
    const int q0 = blockIdx.x * 128;
    const float* Q = g_q + (size_t)bh * T_LEN * HD;
    const float* K = g_k + (size_t)bh * T_LEN * HD;

#pragma unroll
    for (int i = 0; i < 32; i++) {
        int e = tid + i * 256;
        int q = e >> 6, d = e & 63;
        Qt[d][q] = Q[(size_t)(q0 + q) * HD + d];
    }

    float m_run[8], l_run[8];
#pragma unroll
    for (int i = 0; i < 8; i++) { m_run[i] = NEG_BIG; l_run[i] = 0.f; }

    for (int kt = 0; kt < T_LEN; kt += 64) {
        __syncthreads();
#pragma unroll
        for (int i = 0; i < 16; i++) {
            int e = tid + i * 256;
            int k = e >> 6, d = e & 63;
            Kt[d][k] = K[(size_t)(kt + k) * HD + d];
        }
        if (tid < 64) mtile[tid] = mask_at(maskp, b * T_LEN + kt + tid) ? NEG_BIG : 0.f;
        __syncthreads();

        float sacc[8][4];
#pragma unroll
        for (int i = 0; i < 8; i++)
#pragma unroll
            for (int j = 0; j < 4; j++) sacc[i][j] = 0.f;

#pragma unroll 8
        for (int d = 0; d < 64; d++) {
            float4 a0 = *(const float4*)&Qt[d][r0];
            float4 a1 = *(const float4*)&Qt[d][r0 + 4];
            float4 bb = *(const float4*)&Kt[d][c0];
            float av[8] = {a0.x, a0.y, a0.z, a0.w, a1.x, a1.y, a1.z, a1.w};
            float bv[4] = {bb.x, bb.y, bb.z, bb.w};
#pragma unroll
            for (int i = 0; i < 8; i++)
#pragma unroll
                for (int j = 0; j < 4; j++) sacc[i][j] += av[i] * bv[j];
        }

        float msk[4] = {mtile[c0], mtile[c0 + 1], mtile[c0 + 2], mtile[c0 + 3]};
#pragma unroll
        for (int i = 0; i < 8; i++) {
            float s0 = sacc[i][0] + msk[0];
            float s1 = sacc[i][1] + msk[1];
            float s2 = sacc[i][2] + msk[2];
            float s3 = sacc[i][3] + msk[3];
            float mx = fmaxf(fmaxf(s0, s1), fmaxf(s2, s3));
#pragma unroll
            for (int o = 1; o < 16; o <<= 1)
                mx = fmaxf(mx, __shfl_xor_sync(0xffffffffu, mx, o));
            float mnew = fmaxf(m_run[i], mx);
            float ps = __expf(s0 - mnew) + __expf(s1 - mnew) +
                       __expf(s2 - mnew) + __expf(s3 - mnew);
#pragma unroll
            for (int o = 1; o < 16; o <<= 1)
                ps += __shfl_xor_sync(0xffffffffu, ps, o);
            l_run[i] = l_run[i] * __expf(m_run[i] - mnew) + ps;
            m_run[i] = mnew;
        }
    }

    if (tx == 0) {
#pragma unroll
        for (int i = 0; i < 8; i++) {
            int q = q0 + r0 + i;
            g_m[bh * T_LEN + q] = m_run[i];
            g_l[bh * T_LEN + q] = l_run[i];
        }
    }
}

// ---------------- pass B1: ctx = (P/l) @ V, head-interleaved into g_ctx ----------------
__global__ void __launch_bounds__(256)
attn_ctx_kernel(const void* __restrict__ maskp)
{
    extern __shared__ float sm[];
    float (*Qt)[132] = (float (*)[132])sm;                           // [64][132]
    float (*KVt)[68] = (float (*)[68])(sm + 64 * 132);               // [64][68] K^T then V
    float (*Ps)[68]  = (float (*)[68])(sm + 64 * 132 + 64 * 68);     // [128][68]
    float* mrow  = sm + 64 * 132 + 64 * 68 + 128 * 68;               // [128]
    float* linv  = mrow + 128;                                       // [128]
    float* mtile = linv + 128;                                       // [64]

    const int tid = threadIdx.x;
    const int tx = tid & 15, ty = tid >> 4;
    const int r0 = ty * 8, c0 = tx * 4;
    const int bh = blockIdx.y;
    const int b = bh / NH, h = bh % NH;
    const int q0 = blockIdx.x * 128;
    const float* Q = g_q + (size_t)bh * T_LEN * HD;
    const float* K = g_k + (size_t)bh * T_LEN * HD;
    const float* V = g_v + (size_t)bh * T_LEN * HD;

#pragma unroll
    for (int i = 0; i < 32; i++) {
        int e = tid + i * 256;
        int q = e >> 6, d = e & 63;
        Qt[d][q] = Q[(size_t)(q0 + q) * HD + d];
    }
    if (tid < 128) {
        int q = q0 + tid;
        mrow[tid] = g_m[bh * T_LEN + q];
        linv[tid] = 1.0f / g_l[bh * T_LEN + q];
    }

    float oacc[8][4];
#pragma unroll
    for (int i = 0; i < 8; i++)
#pragma unroll
        for (int j = 0; j < 4; j++) oacc[i][j] = 0.f;

    for (int kt = 0; kt < T_LEN; kt += 64) {
        __syncthreads();                        // prev PV reads of KVt/Ps done
#pragma unroll
        for (int i = 0; i < 16; i++) {          // K transposed
            int e = tid + i * 256;
            int k = e >> 6, d = e & 63;
            KVt[d][k] = K[(size_t)(kt + k) * HD + d];
        }
        if (tid < 64) mtile[tid] = mask_at(maskp, b * T_LEN + kt + tid) ? NEG_BIG : 0.f;
        __syncthreads();

        float sacc[8][4];
#pragma unroll
        for (int i = 0; i < 8; i++)
#pragma unroll
            for (int j = 0; j < 4; j++) sacc[i][j] = 0.f;

#pragma unroll 8
        for (int d = 0; d < 64; d++) {
            float4 a0 = *(const float4*)&Qt[d][r0];
            float4 a1 = *(const float4*)&Qt[d][r0 + 4];
            float4 bb = *(const float4*)&KVt[d][c0];
            float av[8] = {a0.x, a0.y, a0.z, a0.w, a1.x, a1.y, a1.z, a1.w};
            float bv[4] = {bb.x, bb.y, bb.z, bb.w};
#pragma unroll
            for (int i = 0; i < 8; i++)
#pragma unroll
                for (int j = 0; j < 4; j++) sacc[i][j] += av[i] * bv[j];
        }
        __syncthreads();                        // done reading K from KVt

        float msk[4] = {mtile[c0], mtile[c0 + 1], mtile[c0 + 2], mtile[c0 + 3]};
#pragma unroll
        for (int i = 0; i < 8; i++) {           // probabilities -> smem (natural layout)
            int q = r0 + i;
            float mi = mrow[q], li = linv[q];
            float4 p;
            p.x = __expf(sacc[i][0] + msk[0] - mi) * li;
            p.y = __expf(sacc[i][1] + msk[1] - mi) * li;
            p.z = __expf(sacc[i][2] + msk[2] - mi) * li;
            p.w = __expf(sacc[i][3] + msk[3] - mi) * li;
            *(float4*)&Ps[q][c0] = p;
        }
#pragma unroll
        for (int i = 0; i < 16; i++) {          // V natural into KVt
            int e = tid + i * 256;
            int k = e >> 6, dv = e & 63;
            KVt[k][dv] = V[(size_t)(kt + k) * HD + dv];
        }
        __syncthreads();

#pragma unroll 8
        for (int k = 0; k < 64; k++) {          // O += P @ V
            float4 bv = *(const float4*)&KVt[k][c0];
#pragma unroll
            for (int i = 0; i < 8; i++) {
                float p = Ps[r0 + i][k];
                oacc[i][0] += p * bv.x;
                oacc[i][1] += p * bv.y;
                oacc[i][2] += p * bv.z;
                oacc[i][3] += p * bv.w;
            }
        }
    }

#pragma unroll
    for (int i = 0; i < 8; i++) {
        int t = q0 + r0 + i;
        size_t row = (size_t)t * BSZ + b;
        float4 v = make_float4(oacc[i][0], oacc[i][1], oacc[i][2], oacc[i][3]);
        *(float4*)&g_ctx[row * EMB + h * HD + c0] = v;
    }
}

// ---------------- pass B2: avg weights = mean_h softmax(S) ----------------
// grid (T/64 k-tiles, T/128 q-tiles, B). One CTA owns its output tile and
// loops all heads -> head-mean accumulates in registers, single write.
__global__ void __launch_bounds__(256)
attn_avgw_kernel(const void* __restrict__ maskp, float* __restrict__ outAvg)
{
    extern __shared__ float sm[];
    float (*Qt)[132] = (float (*)[132])sm;                 // [64][132]
    float (*Kt)[68]  = (float (*)[68])(sm + 64 * 132);     // [64][68]
    float* mrow  = sm + 64 * 132 + 64 * 68;                // [128]
    float* linv  = mrow + 128;                             // [128]
    float* mtile = linv + 128;                             // [64]

    const int tid = threadIdx.x;
    const int tx = tid & 15, ty = tid >> 4;
    const int r0 = ty * 8, c0 = tx * 4;
    const int b = blockIdx.z;
    const int q0 = blockIdx.y * 128;
    const int k0 = blockIdx.x * 64;

    if (tid < 64) mtile[tid] = mask_at(maskp, b * T_LEN + k0 + tid) ? NEG_BIG : 0.f;

    float avg[8][4];
#pragma unroll
    for (int i = 0; i < 8; i++)
#pragma unroll
        for (int j = 0; j < 4; j++) avg[i][j] = 0.f;

    for (int h = 0; h < NH; h++) {
        const int bh = b * NH + h;
        const float* Q = g_q + (size_t)bh * T_LEN * HD;
        const float* K = g_k + (size_t)bh * T_LEN * HD;
        __syncthreads();                        // prev head's reads done
#pragma unroll
        for (int i = 0; i < 32; i++) {
            int e = tid + i * 256;
            int q = e >> 6, d = e & 63;
            Qt[d][q] = Q[(size_t)(q0 + q) * HD + d];
        }
#pragma unroll
        for (int i = 0; i < 16; i++) {
            int e = tid + i * 256;
            int k = e >> 6, d = e & 63;
            Kt[d][k] = K[(size_t)(k0 + k) * HD + d];
        }
        if (tid < 128) {
            int q = q0 + tid;
            mrow[tid] = g_m[bh * T_LEN + q];
            linv[tid] = 1.0f / g_l[bh * T_LEN + q];
        }
        __syncthreads();

        float sacc[8][4];
#pragma unroll
        for (int i = 0; i < 8; i++)
#pragma unroll
            for (int j = 0; j < 4; j++) sacc[i][j] = 0.f;

#pragma unroll 8
        for (int d = 0; d < 64; d++) {
            float4 a0 = *(const float4*)&Qt[d][r0];
            float4 a1 = *(const float4*)&Qt[d][r0 + 4];
            float4 bb = *(const float4*)&Kt[d][c0];
            float av[8] = {a0.x, a0.y, a0.z, a0.w, a1.x, a1.y, a1.z, a1.w};
            float bv[4] = {bb.x, bb.y, bb.z, bb.w};
#pragma unroll
            for (int i = 0; i < 8; i++)
#pragma unroll
                for (int j = 0; j < 4; j++) sacc[i][j] += av[i] * bv[j];
        }

        float msk[4] = {mtile[c0], mtile[c0 + 1], mtile[c0 + 2], mtile[c0 + 3]};
#pragma unroll
        for (int i = 0; i < 8; i++) {
            float mi = mrow[r0 + i], li = linv[r0 + i];
#pragma unroll
            for (int j = 0; j < 4; j++)
                avg[i][j] += __expf(sacc[i][j] + msk[j] - mi) * li;
        }
    }

    const float invH = 1.0f / NH;
#pragma unroll
    for (int i = 0; i < 8; i++) {
        float4 v = make_float4(avg[i][0] * invH, avg[i][1] * invH,
                               avg[i][2] * invH, avg[i][3] * invH);
        size_t row = (size_t)b * T_LEN + (q0 + r0 + i);
        *(float4*)&outAvg[row * T_LEN + k0 + c0] = v;
    }
}

// ---------------- launch ----------------
extern "C" void kernel_launch(void* const* d_in, const int* in_sizes, int n_in,
                              void* d_out, int out_size)
{
    const float* query = (const float*)d_in[0];
    const void*  maskp = d_in[1];
    const float* Wq = (const float*)d_in[2];
    const float* bq = (const float*)d_in[3];
    const float* Wk = (const float*)d_in[4];
    const float* bk = (const float*)d_in[5];
    const float* Wv = (const float*)d_in[6];
    const float* bv = (const float*)d_in[7];
    const float* Wo = (const float*)d_in[8];
    const float* bo = (const float*)d_in[9];
    float* outAttn = (float*)d_out;
    float* outAvg  = outAttn + (size_t)MROWS * EMB;

    float *qp, *kp, *vp, *ctxp;
    cudaGetSymbolAddress((void**)&qp, g_q);
    cudaGetSymbolAddress((void**)&kp, g_k);
    cudaGetSymbolAddress((void**)&vp, g_v);
    cudaGetSymbolAddress((void**)&ctxp, g_ctx);

    probe_mask_kernel<<<1, 256>>>((const unsigned char*)maskp);

    dim3 gp(MROWS / 128, EMB / 64);
    proj_kernel<1><<<gp, 256>>>(query, Wq, bq, qp, SCALING);
    proj_kernel<1><<<gp, 256>>>(query, Wk, bk, kp, 1.0f);
    proj_kernel<1><<<gp, 256>>>(query, Wv, bv, vp, 1.0f);

    const size_t smStats = (size_t)(64 * 132 + 64 * 68 + 64) * sizeof(float);
    cudaFuncSetAttribute(attn_stats_kernel,
                         cudaFuncAttributeMaxDynamicSharedMemorySize, (int)smStats);
    attn_stats_kernel<<<dim3(T_LEN / 128, BHEADS), 256, smStats>>>(maskp);

    const size_t smCtx = (size_t)(64 * 132 + 64 * 68 + 128 * 68 + 128 + 128 + 64) * sizeof(float);
    cudaFuncSetAttribute(attn_ctx_kernel,
                         cudaFuncAttributeMaxDynamicSharedMemorySize, (int)smCtx);
    attn_ctx_kernel<<<dim3(T_LEN / 128, BHEADS), 256, smCtx>>>(maskp);

    proj_kernel<0><<<gp, 256>>>(ctxp, Wo, bo, outAttn, 1.0f);

    const size_t smAvg = (size_t)(64 * 132 + 64 * 68 + 128 + 128 + 64) * sizeof(float);
    cudaFuncSetAttribute(attn_avgw_kernel,
                         cudaFuncAttributeMaxDynamicSharedMemorySize, (int)smAvg);
    attn_avgw_kernel<<<dim3(T_LEN / 64, T_LEN / 128, BSZ), 256, smAvg>>>(maskp, outAvg);
}

// round 3
// speedup vs baseline: 1.7145x; 1.7145x over previous
#include <cuda_runtime.h>
#include <cuda_bf16.h>
#include <cstdint>

#define T_LEN 2048
#define BSZ 2
#define EMB 1280
#define NH 20
#define HD 64
#define BHEADS (BSZ*NH)          /* 40 */
#define MROWS (T_LEN*BSZ)        /* 4096 */
#define SCALING 0.125f           /* 64^-0.5 */
#define NEG_BIG (-1e30f)

// ---------------- scratch (device globals; no allocation allowed) ----------------
__device__ float g_q[(size_t)BHEADS * T_LEN * HD];
__device__ float g_k[(size_t)BHEADS * T_LEN * HD];
__device__ float g_v[(size_t)BHEADS * T_LEN * HD];
__device__ float g_ctx[(size_t)MROWS * EMB];
__device__ float g_m[BHEADS * T_LEN];
__device__ float g_l[BHEADS * T_LEN];
__device__ int   g_mask_u8;
// bf16 split scratch (A buffer reused for X then ctx)
__device__ __nv_bfloat16 g_ahi[(size_t)MROWS * EMB];
__device__ __nv_bfloat16 g_alo[(size_t)MROWS * EMB];
__device__ __nv_bfloat16 g_wthi[4][(size_t)EMB * EMB];
__device__ __nv_bfloat16 g_wtlo[4][(size_t)EMB * EMB];

// ---------------- helpers ----------------
__device__ __forceinline__ uint32_t smem_u32(const void* p) {
    uint32_t a;
    asm("{ .reg .u64 t; cvta.to.shared.u64 t, %1; cvt.u32.u64 %0, t; }" : "=r"(a) : "l"(p));
    return a;
}
#define CP_ASYNC16(saddr, gptr) \
    asm volatile("cp.async.cg.shared.global [%0], [%1], 16;" :: "r"(saddr), "l"(gptr))
#define CP_COMMIT() asm volatile("cp.async.commit_group;")
#define CP_WAIT(n)  asm volatile("cp.async.wait_group %0;" :: "n"(n))

#define LDSM4(r, addr) \
    asm volatile("ldmatrix.sync.aligned.m8n8.x4.shared.b16 {%0,%1,%2,%3}, [%4];" \
        : "=r"((r)[0]),"=r"((r)[1]),"=r"((r)[2]),"=r"((r)[3]) : "r"(addr))
#define LDSM2(r, addr) \
    asm volatile("ldmatrix.sync.aligned.m8n8.x2.shared.b16 {%0,%1}, [%2];" \
        : "=r"((r)[0]),"=r"((r)[1]) : "r"(addr))
#define MMA16816(c, a, b) \
    asm volatile("mma.sync.aligned.m16n8k16.row.col.f32.bf16.bf16.f32 " \
        "{%0,%1,%2,%3},{%4,%5,%6,%7},{%8,%9},{%0,%1,%2,%3};" \
        : "+f"((c)[0]),"+f"((c)[1]),"+f"((c)[2]),"+f"((c)[3]) \
        : "r"((a)[0]),"r"((a)[1]),"r"((a)[2]),"r"((a)[3]), "r"((b)[0]),"r"((b)[1]))

// swizzled smem offset for 64B rows split into 4x16B chunks (conflict-free ldmatrix)
__device__ __forceinline__ uint32_t swz(int row, int c) {
    return (uint32_t)(row * 64 + ((c ^ ((row >> 1) & 3)) << 4));
}

// ---------------- mask dtype probe ----------------
__global__ void probe_mask_kernel(const unsigned char* __restrict__ m)
{
    __shared__ int any;
    if (threadIdx.x == 0) any = 0;
    __syncthreads();
    int acc = 0;
    for (int i = threadIdx.x; i < BSZ * T_LEN; i += blockDim.x) acc |= m[i];
    if (acc) atomicOr(&any, 1);
    __syncthreads();
    if (threadIdx.x == 0) g_mask_u8 = any;
}

__device__ __forceinline__ int mask_at(const void* mp, int idx)
{
    if (g_mask_u8) return ((const unsigned char*)mp)[idx] != 0;
    return ((const int*)mp)[idx] != 0;
}

// ---------------- split-precision conversion: x -> (bf16 hi, bf16 lo) ----------------
__global__ void cvt_split_kernel(const float* __restrict__ x,
                                 __nv_bfloat16* __restrict__ hi,
                                 __nv_bfloat16* __restrict__ lo, int n4)
{
    int i = blockIdx.x * blockDim.x + threadIdx.x;
    if (i >= n4) return;
    float4 v = ((const float4*)x)[i];
    __nv_bfloat16 h0 = __float2bfloat16_rn(v.x);
    __nv_bfloat16 h1 = __float2bfloat16_rn(v.y);
    __nv_bfloat16 h2 = __float2bfloat16_rn(v.z);
    __nv_bfloat16 h3 = __float2bfloat16_rn(v.w);
    __nv_bfloat16 l0 = __float2bfloat16_rn(v.x - __bfloat162float(h0));
    __nv_bfloat16 l1 = __float2bfloat16_rn(v.y - __bfloat162float(h1));
    __nv_bfloat16 l2 = __float2bfloat16_rn(v.z - __bfloat162float(h2));
    __nv_bfloat16 l3 = __float2bfloat16_rn(v.w - __bfloat162float(h3));
    ((__nv_bfloat162*)hi)[i*2]   = __nv_bfloat162(h0, h1);
    ((__nv_bfloat162*)hi)[i*2+1] = __nv_bfloat162(h2, h3);
    ((__nv_bfloat162*)lo)[i*2]   = __nv_bfloat162(l0, l1);
    ((__nv_bfloat162*)lo)[i*2+1] = __nv_bfloat162(l2, l3);
}

// ---------------- transpose + split: W[k][n] f32 -> Wt_hi/lo[n][k] bf16 ----------------
__global__ void tsp_split_kernel(const float* __restrict__ W,
                                 __nv_bfloat16* __restrict__ hi,
                                 __nv_bfloat16* __restrict__ lo)
{
    __shared__ float t[32][33];
    const int k0 = blockIdx.x * 32, n0 = blockIdx.y * 32;
    const int tx = threadIdx.x, ty = threadIdx.y;   // (32, 8)
#pragma unroll
    for (int i = 0; i < 4; i++)
        t[ty + i*8][tx] = W[(size_t)(k0 + ty + i*8) * EMB + n0 + tx];
    __syncthreads();
#pragma unroll
    for (int i = 0; i < 4; i++) {
        float v = t[tx][ty + i*8];
        __nv_bfloat16 h = __float2bfloat16_rn(v);
        __nv_bfloat16 l = __float2bfloat16_rn(v - __bfloat162float(h));
        size_t o = (size_t)(n0 + ty + i*8) * EMB + k0 + tx;
        hi[o] = h; lo[o] = l;
    }
}

// ---------------- mma.sync GEMM: out = (Ahi+Alo)@(Bhi+Blo)^T + bias, *scale ----------
// A: [4096,1280] bf16 K-contig. B(Wt): [1280,1280] bf16 K-contig.
// CTA tile 128x64, BK=32, 8 warps (warp tile 32x32), cp.async 2-stage.
#define BM 128
#define BN 64
#define BK 32
#define NKB (EMB / BK)             /* 40 */
#define OFF_AHI 0
#define OFF_ALO 8192
#define OFF_BHI 16384
#define OFF_BLO 20480
#define STAGE_BYTES 24576
#define GEMM_SMEM (2 * STAGE_BYTES)

template <int OUTMODE>
__global__ void __launch_bounds__(256, 2)
tc_gemm_kernel(const __nv_bfloat16* __restrict__ Ahi, const __nv_bfloat16* __restrict__ Alo,
               const __nv_bfloat16* __restrict__ Bhi, const __nv_bfloat16* __restrict__ Blo,
               const float* __restrict__ bias, float* __restrict__ out, float scale)
{
    extern __shared__ char smem[];
    const uint32_t sb = smem_u32(smem);
    const int tid = threadIdx.x;
    const int wid = tid >> 5, lane = tid & 31;
    const int m0 = blockIdx.x * BM, n0 = blockIdx.y * BN;
    const int wm0 = (wid & 3) * 32;        // warp row offset in tile
    const int wn0 = (wid >> 2) * 32;       // warp col offset in tile

    float acc[2][4][4];
#pragma unroll
    for (int im = 0; im < 2; im++)
#pragma unroll
        for (int in = 0; in < 4; in++)
#pragma unroll
            for (int r = 0; r < 4; r++) acc[im][in][r] = 0.f;

    // per-thread copy assignments
    const int arow0 = tid >> 2, ac = tid & 3;              // + second A chunk at +64 rows
    const int brow  = tid >> 2, bc = tid & 3;              // tid<256 covers 64 rows x 4 chunks

    auto copy_stage = [&](int s, int kb) {
        const uint32_t stg = sb + s * STAGE_BYTES;
        const int k0 = kb * BK;
        // A: 128 rows x 2 (this thread covers rows arow0 and arow0+64)
#pragma unroll
        for (int i = 0; i < 2; i++) {
            int row = arow0 + i * 64;
            const __nv_bfloat16* gh = Ahi + (size_t)(m0 + row) * EMB + k0 + ac * 8;
            const __nv_bfloat16* gl = Alo + (size_t)(m0 + row) * EMB + k0 + ac * 8;
            CP_ASYNC16(stg + OFF_AHI + swz(row, ac), gh);
            CP_ASYNC16(stg + OFF_ALO + swz(row, ac), gl);
        }
        // B: 64 rows
        {
            const __nv_bfloat16* gh = Bhi + (size_t)(n0 + brow) * EMB + k0 + bc * 8;
            const __nv_bfloat16* gl = Blo + (size_t)(n0 + brow) * EMB + k0 + bc * 8;
            CP_ASYNC16(stg + OFF_BHI + swz(brow, bc), gh);
            CP_ASYNC16(stg + OFF_BLO + swz(brow, bc), gl);
        }
    };

    copy_stage(0, 0);
    CP_COMMIT();

    for (int kb = 0; kb < NKB; kb++) {
        const int cur = kb & 1;
        if (kb + 1 < NKB) {
            copy_stage(cur ^ 1, kb + 1);
            CP_COMMIT();
            CP_WAIT(1);
        } else {
            CP_WAIT(0);
        }
        __syncthreads();

        const uint32_t stg = sb + cur * STAGE_BYTES;
#pragma unroll
        for (int ks = 0; ks < 2; ks++) {
            const int kc = ks * 2;
            uint32_t ah[2][4], al[2][4], bh[4][2], bl[4][2];
#pragma unroll
            for (int im = 0; im < 2; im++) {
                int row = wm0 + im * 16 + (lane & 15);
                int c = kc + (lane >> 4);
                LDSM4(ah[im], stg + OFF_AHI + swz(row, c));
                LDSM4(al[im], stg + OFF_ALO + swz(row, c));
            }
#pragma unroll
            for (int in = 0; in < 4; in++) {
                int row = wn0 + in * 8 + (lane & 7);
                int c = kc + ((lane >> 3) & 1);
                LDSM2(bh[in], stg + OFF_BHI + swz(row, c));
                LDSM2(bl[in], stg + OFF_BLO + swz(row, c));
            }
#pragma unroll
            for (int im = 0; im < 2; im++)
#pragma unroll
                for (int in = 0; in < 4; in++) {
                    MMA16816(acc[im][in], ah[im], bh[in]);
                    MMA16816(acc[im][in], al[im], bh[in]);
                    MMA16816(acc[im][in], ah[im], bl[in]);
                }
        }
        __syncthreads();
    }

    // epilogue
#pragma unroll
    for (int im = 0; im < 2; im++) {
        const int r = m0 + wm0 + im * 16 + (lane >> 2);
#pragma unroll
        for (int in = 0; in < 4; in++) {
            const int c = n0 + wn0 + in * 8 + (lane & 3) * 2;
            float2 v0, v1;
            v0.x = (acc[im][in][0] + bias[c])     * scale;
            v0.y = (acc[im][in][1] + bias[c + 1]) * scale;
            v1.x = (acc[im][in][2] + bias[c])     * scale;
            v1.y = (acc[im][in][3] + bias[c + 1]) * scale;
            if (OUTMODE == 0) {
                *(float2*)&out[(size_t)r * EMB + c]       = v0;
                *(float2*)&out[(size_t)(r + 8) * EMB + c] = v1;
            } else {
                int h = c >> 6, d = c & 63;
                {
                    int b = r & 1, t = r >> 1;
                    *(float2*)&out[(((size_t)(b * NH + h)) * T_LEN + t) * HD + d] = v0;
                }
                {
                    int r8 = r + 8;
                    int b = r8 & 1, t = r8 >> 1;
                    *(float2*)&out[(((size_t)(b * NH + h)) * T_LEN + t) * HD + d] = v1;
                }
            }
        }
    }
}

// ---------------- fused flash attention: ctx = softmax(QK^T + mask) @ V -------------
// Online softmax (single pass), also writes g_m / g_l for the avg-weights pass.
__global__ void __launch_bounds__(256)
attn_ctx_kernel(const void* __restrict__ maskp)
{
    extern __shared__ float sm[];
    float (*Qt)[132] = (float (*)[132])sm;                           // [64][132]
    float (*KVt)[68] = (float (*)[68])(sm + 64 * 132);               // [64][68] K^T then V
    float (*Ps)[68]  = (float (*)[68])(sm + 64 * 132 + 64 * 68);     // [128][68]
    float* mtile = sm + 64 * 132 + 64 * 68 + 128 * 68;               // [64]

    const int tid = threadIdx.x;
    const int tx = tid & 15, ty = tid >> 4;
    const int r0 = ty * 8, c0 = tx * 4;
    const int bh = blockIdx.y;
    const int b = bh / NH, h = bh % NH;
    const int q0 = blockIdx.x * 128;
    const float* Q = g_q + (size_t)bh * T_LEN * HD;
    const float* K = g_k + (size_t)bh * T_LEN * HD;
    const float* V = g_v + (size_t)bh * T_LEN * HD;

#pragma unroll
    for (int i = 0; i < 32; i++) {
        int e = tid + i * 256;
        int q = e >> 6, d = e & 63;
        Qt[d][q] = Q[(size_t)(q0 + q) * HD + d];
    }

    float oacc[8][4];
    float m_run[8], l_run[8];
#pragma unroll
    for (int i = 0; i < 8; i++) {
        m_run[i] = NEG_BIG; l_run[i] = 0.f;
#pragma unroll
        for (int j = 0; j < 4; j++) oacc[i][j] = 0.f;
    }

    for (int kt = 0; kt < T_LEN; kt += 64) {
        __syncthreads();                        // prev PV reads of KVt/Ps done
#pragma unroll
        for (int i = 0; i < 16; i++) {          // K transposed
            int e = tid + i * 256;
            int k = e >> 6, d = e & 63;
            KVt[d][k] = K[(size_t)(kt + k) * HD + d];
        }
        if (tid < 64) mtile[tid] = mask_at(maskp, b * T_LEN + kt + tid) ? NEG_BIG : 0.f;
        __syncthreads();

        float sacc[8][4];
#pragma unroll
        for (int i = 0; i < 8; i++)
#pragma unroll
            for (int j = 0; j < 4; j++) sacc[i][j] = 0.f;

#pragma unroll 8
        for (int d = 0; d < 64; d++) {
            float4 a0 = *(const float4*)&Qt[d][r0];
            float4 a1 = *(const float4*)&Qt[d][r0 + 4];
            float4 bb = *(const float4*)&KVt[d][c0];
            float av[8] = {a0.x, a0.y, a0.z, a0.w, a1.x, a1.y, a1.z, a1.w};
            float bv[4] = {bb.x, bb.y, bb.z, bb.w};
#pragma unroll
            for (int i = 0; i < 8; i++)
#pragma unroll
                for (int j = 0; j < 4; j++) sacc[i][j] += av[i] * bv[j];
        }
        __syncthreads();                        // done reading K from KVt

        float msk[4] = {mtile[c0], mtile[c0 + 1], mtile[c0 + 2], mtile[c0 + 3]};
#pragma unroll
        for (int i = 0; i < 8; i++) {
            float s0 = sacc[i][0] + msk[0];
            float s1 = sacc[i][1] + msk[1];
            float s2 = sacc[i][2] + msk[2];
            float s3 = sacc[i][3] + msk[3];
            float mx = fmaxf(fmaxf(s0, s1), fmaxf(s2, s3));
#pragma unroll
            for (int o = 1; o < 16; o <<= 1)
                mx = fmaxf(mx, __shfl_xor_sync(0xffffffffu, mx, o));
            float mnew = fmaxf(m_run[i], mx);
            float scl = __expf(m_run[i] - mnew);
            float4 p;
            p.x = __expf(s0 - mnew);
            p.y = __expf(s1 - mnew);
            p.z = __expf(s2 - mnew);
            p.w = __expf(s3 - mnew);
            float ps = p.x + p.y + p.z + p.w;
#pragma unroll
            for (int o = 1; o < 16; o <<= 1)
                ps += __shfl_xor_sync(0xffffffffu, ps, o);
            l_run[i] = l_run[i] * scl + ps;
            m_run[i] = mnew;
#pragma unroll
            for (int j = 0; j < 4; j++) oacc[i][j] *= scl;
            *(float4*)&Ps[r0 + i][c0] = p;
        }
#pragma unroll
        for (int i = 0; i < 16; i++) {          // V natural into KVt
            int e = tid + i * 256;
            int k = e >> 6, dv = e & 63;
            KVt[k][dv] = V[(size_t)(kt + k) * HD + dv];
        }
        __syncthreads();

#pragma unroll 8
        for (int k = 0; k < 64; k++) {          // O += P @ V
            float4 bv = *(const float4*)&KVt[k][c0];
#pragma unroll
            for (int i = 0; i < 8; i++) {
                float p = Ps[r0 + i][k];
                oacc[i][0] += p * bv.x;
                oacc[i][1] += p * bv.y;
                oacc[i][2] += p * bv.z;
                oacc[i][3] += p * bv.w;
            }
        }
    }

#pragma unroll
    for (int i = 0; i < 8; i++) {
        int t = q0 + r0 + i;
        float linv = 1.0f / l_run[i];
        size_t row = (size_t)t * BSZ + b;
        float4 v = make_float4(oacc[i][0] * linv, oacc[i][1] * linv,
                               oacc[i][2] * linv, oacc[i][3] * linv);
        *(float4*)&g_ctx[row * EMB + h * HD + c0] = v;
        if (tx == 0) {
            g_m[bh * T_LEN + t] = m_run[i];
            g_l[bh * T_LEN + t] = l_run[i];
        }
    }
}

// ---------------- pass B2: avg weights = mean_h softmax(S) ----------------
__global__ void __launch_bounds__(256)
attn_avgw_kernel(const void* __restrict__ maskp, float* __restrict__ outAvg)
{
    extern __shared__ float sm[];
    float (*Qt)[132] = (float (*)[132])sm;                 // [64][132]
    float (*Kt)[68]  = (float (*)[68])(sm + 64 * 132);     // [64][68]
    float* mrow  = sm + 64 * 132 + 64 * 68;                // [128]
    float* linv  = mrow + 128;                             // [128]
    float* mtile = linv + 128;                             // [64]

    const int tid = threadIdx.x;
    const int tx = tid & 15, ty = tid >> 4;
    const int r0 = ty * 8, c0 = tx * 4;
    const int b = blockIdx.z;
    const int q0 = blockIdx.y * 128;
    const int k0 = blockIdx.x * 64;

    if (tid < 64) mtile[tid] = mask_at(maskp, b * T_LEN + k0 + tid) ? NEG_BIG : 0.f;

    float avg[8][4];
#pragma unroll
    for (int i = 0; i < 8; i++)
#pragma unroll
        for (int j = 0; j < 4; j++) avg[i][j] = 0.f;

    for (int h = 0; h < NH; h++) {
        const int bh = b * NH + h;
        const float* Q = g_q + (size_t)bh * T_LEN * HD;
        const float* K = g_k + (size_t)bh * T_LEN * HD;
        __syncthreads();                        // prev head's reads done
#pragma unroll
        for (int i = 0; i < 32; i++) {
            int e = tid + i * 256;
            int q = e >> 6, d = e & 63;
            Qt[d][q] = Q[(size_t)(q0 + q) * HD + d];
        }
#pragma unroll
        for (int i = 0; i < 16; i++) {
            int e = tid + i * 256;
            int k = e >> 6, d = e & 63;
            Kt[d][k] = K[(size_t)(k0 + k) * HD + d];
        }
        if (tid < 128) {
            int q = q0 + tid;
            mrow[tid] = g_m[bh * T_LEN + q];
            linv[tid] = 1.0f / g_l[bh * T_LEN + q];
        }
        __syncthreads();

        float sacc[8][4];
#pragma unroll
        for (int i = 0; i < 8; i++)
#pragma unroll
            for (int j = 0; j < 4; j++) sacc[i][j] = 0.f;

#pragma unroll 8
        for (int d = 0; d < 64; d++) {
            float4 a0 = *(const float4*)&Qt[d][r0];
            float4 a1 = *(const float4*)&Qt[d][r0 + 4];
            float4 bb = *(const float4*)&Kt[d][c0];
            float av[8] = {a0.x, a0.y, a0.z, a0.w, a1.x, a1.y, a1.z, a1.w};
            float bv[4] = {bb.x, bb.y, bb.z, bb.w};
#pragma unroll
            for (int i = 0; i < 8; i++)
#pragma unroll
                for (int j = 0; j < 4; j++) sacc[i][j] += av[i] * bv[j];
        }

        float msk[4] = {mtile[c0], mtile[c0 + 1], mtile[c0 + 2], mtile[c0 + 3]};
#pragma unroll
        for (int i = 0; i < 8; i++) {
            float mi = mrow[r0 + i], li = linv[r0 + i];
#pragma unroll
            for (int j = 0; j < 4; j++)
                avg[i][j] += __expf(sacc[i][j] + msk[j] - mi) * li;
        }
    }

    const float invH = 1.0f / NH;
#pragma unroll
    for (int i = 0; i < 8; i++) {
        float4 v = make_float4(avg[i][0] * invH, avg[i][1] * invH,
                               avg[i][2] * invH, avg[i][3] * invH);
        size_t row = (size_t)b * T_LEN + (q0 + r0 + i);
        *(float4*)&outAvg[row * T_LEN + k0 + c0] = v;
    }
}

// ---------------- launch ----------------
extern "C" void kernel_launch(void* const* d_in, const int* in_sizes, int n_in,
                              void* d_out, int out_size)
{
    const float* query = (const float*)d_in[0];
    const void*  maskp = d_in[1];
    const float* Wq = (const float*)d_in[2];
    const float* bq = (const float*)d_in[3];
    const float* Wk = (const float*)d_in[4];
    const float* bk = (const float*)d_in[5];
    const float* Wv = (const float*)d_in[6];
    const float* bv = (const float*)d_in[7];
    const float* Wo = (const float*)d_in[8];
    const float* bo = (const float*)d_in[9];
    float* outAttn = (float*)d_out;
    float* outAvg  = outAttn + (size_t)MROWS * EMB;

    float *qp, *kp, *vp, *ctxp;
    __nv_bfloat16 *ahi, *alo, *wthi, *wtlo;
    cudaGetSymbolAddress((void**)&qp, g_q);
    cudaGetSymbolAddress((void**)&kp, g_k);
    cudaGetSymbolAddress((void**)&vp, g_v);
    cudaGetSymbolAddress((void**)&ctxp, g_ctx);
    cudaGetSymbolAddress((void**)&ahi, g_ahi);
    cudaGetSymbolAddress((void**)&alo, g_alo);
    cudaGetSymbolAddress((void**)&wthi, g_wthi);
    cudaGetSymbolAddress((void**)&wtlo, g_wtlo);

    probe_mask_kernel<<<1, 256>>>((const unsigned char*)maskp);

    // conversions: X split + 4 weight transpose-splits
    const int n4 = MROWS * EMB / 4;
    cvt_split_kernel<<<(n4 + 255) / 256, 256>>>(query, ahi, alo, n4);
    const size_t WSZ = (size_t)EMB * EMB;
    dim3 tg(EMB / 32, EMB / 32), tb(32, 8);
    tsp_split_kernel<<<tg, tb>>>(Wq, wthi + 0 * WSZ, wtlo + 0 * WSZ);
    tsp_split_kernel<<<tg, tb>>>(Wk, wthi + 1 * WSZ, wtlo + 1 * WSZ);
    tsp_split_kernel<<<tg, tb>>>(Wv, wthi + 2 * WSZ, wtlo + 2 * WSZ);
    tsp_split_kernel<<<tg, tb>>>(Wo, wthi + 3 * WSZ, wtlo + 3 * WSZ);

    cudaFuncSetAttribute(tc_gemm_kernel<0>, cudaFuncAttributeMaxDynamicSharedMemorySize, GEMM_SMEM);
    cudaFuncSetAttribute(tc_gemm_kernel<1>, cudaFuncAttributeMaxDynamicSharedMemorySize, GEMM_SMEM);

    dim3 gg(MROWS / BM, EMB / BN);
    tc_gemm_kernel<1><<<gg, 256, GEMM_SMEM>>>(ahi, alo, wthi + 0 * WSZ, wtlo + 0 * WSZ, bq, qp, SCALING);
    tc_gemm_kernel<1><<<gg, 256, GEMM_SMEM>>>(ahi, alo, wthi + 1 * WSZ, wtlo + 1 * WSZ, bk, kp, 1.0f);
    tc_gemm_kernel<1><<<gg, 256, GEMM_SMEM>>>(ahi, alo, wthi + 2 * WSZ, wtlo + 2 * WSZ, bv, vp, 1.0f);

    const size_t smCtx = (size_t)(64 * 132 + 64 * 68 + 128 * 68 + 64) * sizeof(float);
    cudaFuncSetAttribute(attn_ctx_kernel, cudaFuncAttributeMaxDynamicSharedMemorySize, (int)smCtx);
    attn_ctx_kernel<<<dim3(T_LEN / 128, BHEADS), 256, smCtx>>>(maskp);

    cvt_split_kernel<<<(n4 + 255) / 256, 256>>>(ctxp, ahi, alo, n4);
    tc_gemm_kernel<0><<<gg, 256, GEMM_SMEM>>>(ahi, alo, wthi + 3 * WSZ, wtlo + 3 * WSZ, bo, outAttn, 1.0f);

    const size_t smAvg = (size_t)(64 * 132 + 64 * 68 + 128 + 128 + 64) * sizeof(float);
    cudaFuncSetAttribute(attn_avgw_kernel, cudaFuncAttributeMaxDynamicSharedMemorySize, (int)smAvg);
    attn_avgw_kernel<<<dim3(T_LEN / 64, T_LEN / 128, BSZ), 256, smAvg>>>(maskp, outAvg);
}

// round 4
// speedup vs baseline: 3.1515x; 1.8382x over previous
#include <cuda_runtime.h>
#include <cuda_bf16.h>
#include <cstdint>

#define T_LEN 2048
#define BSZ 2
#define EMB 1280
#define NH 20
#define HD 64
#define BHEADS (BSZ*NH)          /* 40 */
#define MROWS (T_LEN*BSZ)        /* 4096 */
#define SCALING 0.125f           /* 64^-0.5 */
#define NEG_BIG (-1e30f)

// ---------------- scratch (device globals; no allocation allowed) ----------------
__device__ __nv_bfloat16 g_qhi[(size_t)BHEADS * T_LEN * HD];
__device__ __nv_bfloat16 g_qlo[(size_t)BHEADS * T_LEN * HD];
__device__ __nv_bfloat16 g_khi[(size_t)BHEADS * T_LEN * HD];
__device__ __nv_bfloat16 g_klo[(size_t)BHEADS * T_LEN * HD];
__device__ __nv_bfloat16 g_vhi[(size_t)BHEADS * T_LEN * HD];
__device__ __nv_bfloat16 g_vlo[(size_t)BHEADS * T_LEN * HD];
__device__ float g_ctx[(size_t)MROWS * EMB];
__device__ float g_m[BHEADS * T_LEN];
__device__ float g_l[BHEADS * T_LEN];
__device__ float g_maskf[BSZ * T_LEN];
__device__ __nv_bfloat16 g_ahi[(size_t)MROWS * EMB];
__device__ __nv_bfloat16 g_alo[(size_t)MROWS * EMB];
__device__ __nv_bfloat16 g_wthi[4][(size_t)EMB * EMB];
__device__ __nv_bfloat16 g_wtlo[4][(size_t)EMB * EMB];

// ---------------- helpers ----------------
__device__ __forceinline__ uint32_t smem_u32(const void* p) {
    uint32_t a;
    asm("{ .reg .u64 t; cvta.to.shared.u64 t, %1; cvt.u32.u64 %0, t; }" : "=r"(a) : "l"(p));
    return a;
}
#define CP_ASYNC16(saddr, gptr) \
    asm volatile("cp.async.cg.shared.global [%0], [%1], 16;" :: "r"(saddr), "l"(gptr))
#define CP_COMMIT() asm volatile("cp.async.commit_group;")
#define CP_WAIT(n)  asm volatile("cp.async.wait_group %0;" :: "n"(n))

#define LDSM4(r, addr) \
    asm volatile("ldmatrix.sync.aligned.m8n8.x4.shared.b16 {%0,%1,%2,%3}, [%4];" \
        : "=r"((r)[0]),"=r"((r)[1]),"=r"((r)[2]),"=r"((r)[3]) : "r"(addr))
#define LDSM2(r, addr) \
    asm volatile("ldmatrix.sync.aligned.m8n8.x2.shared.b16 {%0,%1}, [%2];" \
        : "=r"((r)[0]),"=r"((r)[1]) : "r"(addr))
#define LDSM2T(r, addr) \
    asm volatile("ldmatrix.sync.aligned.m8n8.x2.trans.shared.b16 {%0,%1}, [%2];" \
        : "=r"((r)[0]),"=r"((r)[1]) : "r"(addr))
#define MMA16816(c, a, b) \
    asm volatile("mma.sync.aligned.m16n8k16.row.col.f32.bf16.bf16.f32 " \
        "{%0,%1,%2,%3},{%4,%5,%6,%7},{%8,%9},{%0,%1,%2,%3};" \
        : "+f"((c)[0]),"+f"((c)[1]),"+f"((c)[2]),"+f"((c)[3]) \
        : "r"((a)[0]),"r"((a)[1]),"r"((a)[2]),"r"((a)[3]), "r"((b)[0]),"r"((b)[1]))

// 64B-row swizzle (GEMM tiles)
__device__ __forceinline__ uint32_t swz(int row, int c) {
    return (uint32_t)(row * 64 + ((c ^ ((row >> 1) & 3)) << 4));
}
// 128B-row swizzle (attention tiles, HD=64 bf16 per row)
__device__ __forceinline__ uint32_t swz128(int row, int c) {
    return (uint32_t)(row * 128 + ((c ^ (row & 7)) << 4));
}

__device__ __forceinline__ uint32_t pack_bf2(__nv_bfloat16 a, __nv_bfloat16 b) {
    __nv_bfloat162 t(a, b);
    return *reinterpret_cast<uint32_t*>(&t);
}
__device__ __forceinline__ void splitpack(float x, float y, uint32_t& hi, uint32_t& lo) {
    __nv_bfloat16 hx = __float2bfloat16_rn(x), hy = __float2bfloat16_rn(y);
    __nv_bfloat16 lx = __float2bfloat16_rn(x - __bfloat162float(hx));
    __nv_bfloat16 ly = __float2bfloat16_rn(y - __bfloat162float(hy));
    hi = pack_bf2(hx, hy);
    lo = pack_bf2(lx, ly);
}

// ---------------- mask -> float (-1e30 / 0), dtype-probing ----------------
__global__ void maskf_build_kernel(const unsigned char* __restrict__ m)
{
    __shared__ int any;
    if (threadIdx.x == 0) any = 0;
    __syncthreads();
    int acc = 0;
    for (int i = threadIdx.x; i < BSZ * T_LEN; i += blockDim.x) acc |= m[i];
    if (acc) atomicOr(&any, 1);
    __syncthreads();
    const int u8 = any;
    for (int i = threadIdx.x; i < BSZ * T_LEN; i += blockDim.x) {
        int v = u8 ? (m[i] != 0) : (((const int*)m)[i] != 0);
        g_maskf[i] = v ? NEG_BIG : 0.f;
    }
}

// ---------------- split-precision conversion: x -> (bf16 hi, bf16 lo) ----------------
__global__ void cvt_split_kernel(const float* __restrict__ x,
                                 __nv_bfloat16* __restrict__ hi,
                                 __nv_bfloat16* __restrict__ lo, int n4)
{
    int i = blockIdx.x * blockDim.x + threadIdx.x;
    if (i >= n4) return;
    float4 v = ((const float4*)x)[i];
    __nv_bfloat16 h0 = __float2bfloat16_rn(v.x);
    __nv_bfloat16 h1 = __float2bfloat16_rn(v.y);
    __nv_bfloat16 h2 = __float2bfloat16_rn(v.z);
    __nv_bfloat16 h3 = __float2bfloat16_rn(v.w);
    __nv_bfloat16 l0 = __float2bfloat16_rn(v.x - __bfloat162float(h0));
    __nv_bfloat16 l1 = __float2bfloat16_rn(v.y - __bfloat162float(h1));
    __nv_bfloat16 l2 = __float2bfloat16_rn(v.z - __bfloat162float(h2));
    __nv_bfloat16 l3 = __float2bfloat16_rn(v.w - __bfloat162float(h3));
    ((__nv_bfloat162*)hi)[i*2]   = __nv_bfloat162(h0, h1);
    ((__nv_bfloat162*)hi)[i*2+1] = __nv_bfloat162(h2, h3);
    ((__nv_bfloat162*)lo)[i*2]   = __nv_bfloat162(l0, l1);
    ((__nv_bfloat162*)lo)[i*2+1] = __nv_bfloat162(l2, l3);
}

// ---------------- transpose + split: W[k][n] f32 -> Wt_hi/lo[n][k] bf16 ----------------
__global__ void tsp_split_kernel(const float* __restrict__ W,
                                 __nv_bfloat16* __restrict__ hi,
                                 __nv_bfloat16* __restrict__ lo)
{
    __shared__ float t[32][33];
    const int k0 = blockIdx.x * 32, n0 = blockIdx.y * 32;
    const int tx = threadIdx.x, ty = threadIdx.y;   // (32, 8)
#pragma unroll
    for (int i = 0; i < 4; i++)
        t[ty + i*8][tx] = W[(size_t)(k0 + ty + i*8) * EMB + n0 + tx];
    __syncthreads();
#pragma unroll
    for (int i = 0; i < 4; i++) {
        float v = t[tx][ty + i*8];
        __nv_bfloat16 h = __float2bfloat16_rn(v);
        __nv_bfloat16 l = __float2bfloat16_rn(v - __bfloat162float(h));
        size_t o = (size_t)(n0 + ty + i*8) * EMB + k0 + tx;
        hi[o] = h; lo[o] = l;
    }
}

// ---------------- mma.sync GEMM ----------
// OUTMODE 0: f32 row-major out. OUTMODE 1: split bf16 head-major (ohi/olo).
#define BM 128
#define BN 64
#define BK 32
#define NKB (EMB / BK)             /* 40 */
#define OFF_AHI 0
#define OFF_ALO 8192
#define OFF_BHI 16384
#define OFF_BLO 20480
#define STAGE_BYTES 24576
#define GEMM_SMEM (2 * STAGE_BYTES)

template <int OUTMODE>
__global__ void __launch_bounds__(256, 2)
tc_gemm_kernel(const __nv_bfloat16* __restrict__ Ahi, const __nv_bfloat16* __restrict__ Alo,
               const __nv_bfloat16* __restrict__ Bhi, const __nv_bfloat16* __restrict__ Blo,
               const float* __restrict__ bias, float* __restrict__ out,
               __nv_bfloat16* __restrict__ ohi, __nv_bfloat16* __restrict__ olo, float scale)
{
    extern __shared__ char smem[];
    const uint32_t sb = smem_u32(smem);
    const int tid = threadIdx.x;
    const int wid = tid >> 5, lane = tid & 31;
    const int m0 = blockIdx.x * BM, n0 = blockIdx.y * BN;
    const int wm0 = (wid & 3) * 32;
    const int wn0 = (wid >> 2) * 32;

    float acc[2][4][4];
#pragma unroll
    for (int im = 0; im < 2; im++)
#pragma unroll
        for (int in = 0; in < 4; in++)
#pragma unroll
            for (int r = 0; r < 4; r++) acc[im][in][r] = 0.f;

    const int arow0 = tid >> 2, ac = tid & 3;
    const int brow  = tid >> 2, bc = tid & 3;

    auto copy_stage = [&](int s, int kb) {
        const uint32_t stg = sb + s * STAGE_BYTES;
        const int k0 = kb * BK;
#pragma unroll
        for (int i = 0; i < 2; i++) {
            int row = arow0 + i * 64;
            const __nv_bfloat16* gh = Ahi + (size_t)(m0 + row) * EMB + k0 + ac * 8;
            const __nv_bfloat16* gl = Alo + (size_t)(m0 + row) * EMB + k0 + ac * 8;
            CP_ASYNC16(stg + OFF_AHI + swz(row, ac), gh);
            CP_ASYNC16(stg + OFF_ALO + swz(row, ac), gl);
        }
        {
            const __nv_bfloat16* gh = Bhi + (size_t)(n0 + brow) * EMB + k0 + bc * 8;
            const __nv_bfloat16* gl = Blo + (size_t)(n0 + brow) * EMB + k0 + bc * 8;
            CP_ASYNC16(stg + OFF_BHI + swz(brow, bc), gh);
            CP_ASYNC16(stg + OFF_BLO + swz(brow, bc), gl);
        }
    };

    copy_stage(0, 0);
    CP_COMMIT();

    for (int kb = 0; kb < NKB; kb++) {
        const int cur = kb & 1;
        if (kb + 1 < NKB) {
            copy_stage(cur ^ 1, kb + 1);
            CP_COMMIT();
            CP_WAIT(1);
        } else {
            CP_WAIT(0);
        }
        __syncthreads();

        const uint32_t stg = sb + cur * STAGE_BYTES;
#pragma unroll
        for (int ks = 0; ks < 2; ks++) {
            const int kc = ks * 2;
            uint32_t ah[2][4], al[2][4], bh[4][2], bl[4][2];
#pragma unroll
            for (int im = 0; im < 2; im++) {
                int row = wm0 + im * 16 + (lane & 15);
                int c = kc + (lane >> 4);
                LDSM4(ah[im], stg + OFF_AHI + swz(row, c));
                LDSM4(al[im], stg + OFF_ALO + swz(row, c));
            }
#pragma unroll
            for (int in = 0; in < 4; in++) {
                int row = wn0 + in * 8 + (lane & 7);
                int c = kc + ((lane >> 3) & 1);
                LDSM2(bh[in], stg + OFF_BHI + swz(row, c));
                LDSM2(bl[in], stg + OFF_BLO + swz(row, c));
            }
#pragma unroll
            for (int im = 0; im < 2; im++)
#pragma unroll
                for (int in = 0; in < 4; in++) {
                    MMA16816(acc[im][in], ah[im], bh[in]);
                    MMA16816(acc[im][in], al[im], bh[in]);
                    MMA16816(acc[im][in], ah[im], bl[in]);
                }
        }
        __syncthreads();
    }

    // epilogue
#pragma unroll
    for (int im = 0; im < 2; im++) {
        const int r = m0 + wm0 + im * 16 + (lane >> 2);
#pragma unroll
        for (int in = 0; in < 4; in++) {
            const int c = n0 + wn0 + in * 8 + (lane & 3) * 2;
            float v00 = (acc[im][in][0] + bias[c])     * scale;
            float v01 = (acc[im][in][1] + bias[c + 1]) * scale;
            float v10 = (acc[im][in][2] + bias[c])     * scale;
            float v11 = (acc[im][in][3] + bias[c + 1]) * scale;
            if (OUTMODE == 0) {
                *(float2*)&out[(size_t)r * EMB + c]       = make_float2(v00, v01);
                *(float2*)&out[(size_t)(r + 8) * EMB + c] = make_float2(v10, v11);
            } else {
                int hh = c >> 6, d = c & 63;
                uint32_t h2, l2;
                {
                    int b = r & 1, t = r >> 1;
                    size_t base = (((size_t)(b * NH + hh)) * T_LEN + t) * HD + d;
                    splitpack(v00, v01, h2, l2);
                    *(uint32_t*)&ohi[base] = h2;
                    *(uint32_t*)&olo[base] = l2;
                }
                {
                    int r8 = r + 8;
                    int b = r8 & 1, t = r8 >> 1;
                    size_t base = (((size_t)(b * NH + hh)) * T_LEN + t) * HD + d;
                    splitpack(v10, v11, h2, l2);
                    *(uint32_t*)&ohi[base] = h2;
                    *(uint32_t*)&olo[base] = l2;
                }
            }
        }
    }
}

// ---------------- tensor-core flash attention: ctx = softmax(QK^T+mask) @ V ----------
// CTA: 128 q-rows x 1 head. 8 warps, each 16 q-rows x full 64-k tile.
#define CTX_OFF_QH 0
#define CTX_OFF_QL 16384
#define CTX_OFF_STG 32768
#define CTX_STAGE 32768
#define CTX_OFF_KH 0
#define CTX_OFF_KL 8192
#define CTX_OFF_VH 16384
#define CTX_OFF_VL 24576
#define CTX_SMEM (CTX_OFF_STG + 2 * CTX_STAGE)   /* 98304 */

__global__ void __launch_bounds__(256, 1)
attn_ctx_mma()
{
    extern __shared__ char smem[];
    const uint32_t sb = smem_u32(smem);
    const int tid = threadIdx.x, w = tid >> 5, lane = tid & 31;
    const int wq0 = w * 16;
    const int bh = blockIdx.y, b = bh / NH, hh = bh % NH;
    const int q0 = blockIdx.x * 128;
    const __nv_bfloat16* Qh = g_qhi + ((size_t)bh * T_LEN + q0) * HD;
    const __nv_bfloat16* Ql = g_qlo + ((size_t)bh * T_LEN + q0) * HD;
    const __nv_bfloat16* Kh = g_khi + (size_t)bh * T_LEN * HD;
    const __nv_bfloat16* Kl = g_klo + (size_t)bh * T_LEN * HD;
    const __nv_bfloat16* Vh = g_vhi + (size_t)bh * T_LEN * HD;
    const __nv_bfloat16* Vl = g_vlo + (size_t)bh * T_LEN * HD;
    const float* mrow = g_maskf + b * T_LEN;

    // Q tile copy (hi+lo), 128 rows x 8 chunks each
#pragma unroll
    for (int i = 0; i < 4; i++) {
        int e = tid + i * 256;
        int row = e >> 3, c = e & 7;
        size_t g = (size_t)row * HD + c * 8;
        CP_ASYNC16(sb + CTX_OFF_QH + swz128(row, c), Qh + g);
        CP_ASYNC16(sb + CTX_OFF_QL + swz128(row, c), Ql + g);
    }
    CP_COMMIT();

    auto copy_kv = [&](int s, int kt) {
        uint32_t stg = sb + CTX_OFF_STG + s * CTX_STAGE;
#pragma unroll
        for (int i = 0; i < 2; i++) {
            int e = tid + i * 256;
            int row = e >> 3, c = e & 7;
            size_t g = (size_t)(kt * 64 + row) * HD + c * 8;
            uint32_t sw = swz128(row, c);
            CP_ASYNC16(stg + CTX_OFF_KH + sw, Kh + g);
            CP_ASYNC16(stg + CTX_OFF_KL + sw, Kl + g);
            CP_ASYNC16(stg + CTX_OFF_VH + sw, Vh + g);
            CP_ASYNC16(stg + CTX_OFF_VL + sw, Vl + g);
        }
    };
    copy_kv(0, 0);
    CP_COMMIT();
    CP_WAIT(1);                 // Q group done
    __syncthreads();

    // Q fragments, register-resident
    uint32_t qfh[4][4], qfl[4][4];
#pragma unroll
    for (int kc = 0; kc < 4; kc++) {
        int row = wq0 + (lane & 15), c = 2 * kc + (lane >> 4);
        LDSM4(qfh[kc], sb + CTX_OFF_QH + swz128(row, c));
        LDSM4(qfl[kc], sb + CTX_OFF_QL + swz128(row, c));
    }

    float m0 = NEG_BIG, m1 = NEG_BIG, l0 = 0.f, l1 = 0.f;
    float O[8][4];
#pragma unroll
    for (int j = 0; j < 8; j++)
#pragma unroll
        for (int r = 0; r < 4; r++) O[j][r] = 0.f;

    const int cc = (lane & 3) * 2;

    for (int kt = 0; kt < T_LEN / 64; kt++) {
        const int cur = kt & 1;
        if (kt + 1 < T_LEN / 64) { copy_kv(cur ^ 1, kt + 1); CP_COMMIT(); CP_WAIT(1); }
        else CP_WAIT(0);
        __syncthreads();
        const uint32_t stg = sb + CTX_OFF_STG + cur * CTX_STAGE;

        float S[8][4];
#pragma unroll
        for (int j = 0; j < 8; j++)
#pragma unroll
            for (int r = 0; r < 4; r++) S[j][r] = 0.f;

#pragma unroll
        for (int kc = 0; kc < 4; kc++) {
#pragma unroll
            for (int j = 0; j < 8; j++) {
                uint32_t kfh[2], kfl[2];
                int rowk = 8 * j + (lane & 7), ck = 2 * kc + ((lane >> 3) & 1);
                uint32_t sw = swz128(rowk, ck);
                LDSM2(kfh, stg + CTX_OFF_KH + sw);
                LDSM2(kfl, stg + CTX_OFF_KL + sw);
                MMA16816(S[j], qfh[kc], kfh);
                MMA16816(S[j], qfl[kc], kfh);
                MMA16816(S[j], qfh[kc], kfl);
            }
        }

        // mask + online softmax (rows r = lane>>2 and r+8)
        const int kb = kt * 64 + cc;
#pragma unroll
        for (int j = 0; j < 8; j++) {
            float2 mv = *(const float2*)&mrow[kb + 8 * j];
            S[j][0] += mv.x; S[j][1] += mv.y; S[j][2] += mv.x; S[j][3] += mv.y;
        }
        float rm0 = fmaxf(S[0][0], S[0][1]), rm1 = fmaxf(S[0][2], S[0][3]);
#pragma unroll
        for (int j = 1; j < 8; j++) {
            rm0 = fmaxf(rm0, fmaxf(S[j][0], S[j][1]));
            rm1 = fmaxf(rm1, fmaxf(S[j][2], S[j][3]));
        }
        rm0 = fmaxf(rm0, __shfl_xor_sync(0xffffffffu, rm0, 1));
        rm0 = fmaxf(rm0, __shfl_xor_sync(0xffffffffu, rm0, 2));
        rm1 = fmaxf(rm1, __shfl_xor_sync(0xffffffffu, rm1, 1));
        rm1 = fmaxf(rm1, __shfl_xor_sync(0xffffffffu, rm1, 2));
        float mn0 = fmaxf(m0, rm0), mn1 = fmaxf(m1, rm1);
        float sc0 = __expf(m0 - mn0), sc1 = __expf(m1 - mn1);
        float rs0 = 0.f, rs1 = 0.f;
#pragma unroll
        for (int j = 0; j < 8; j++) {
            S[j][0] = __expf(S[j][0] - mn0);
            S[j][1] = __expf(S[j][1] - mn0);
            S[j][2] = __expf(S[j][2] - mn1);
            S[j][3] = __expf(S[j][3] - mn1);
            rs0 += S[j][0] + S[j][1];
            rs1 += S[j][2] + S[j][3];
        }
        rs0 += __shfl_xor_sync(0xffffffffu, rs0, 1);
        rs0 += __shfl_xor_sync(0xffffffffu, rs0, 2);
        rs1 += __shfl_xor_sync(0xffffffffu, rs1, 1);
        rs1 += __shfl_xor_sync(0xffffffffu, rs1, 2);
        l0 = l0 * sc0 + rs0;  m0 = mn0;
        l1 = l1 * sc1 + rs1;  m1 = mn1;
#pragma unroll
        for (int j = 0; j < 8; j++) {
            O[j][0] *= sc0; O[j][1] *= sc0; O[j][2] *= sc1; O[j][3] *= sc1;
        }

        // P @ V : acc layout == A-fragment layout
#pragma unroll
        for (int kc2 = 0; kc2 < 4; kc2++) {
            const int j0 = 2 * kc2, j1 = j0 + 1;
            uint32_t pah[4], pal[4];
            splitpack(S[j0][0], S[j0][1], pah[0], pal[0]);
            splitpack(S[j0][2], S[j0][3], pah[1], pal[1]);
            splitpack(S[j1][0], S[j1][1], pah[2], pal[2]);
            splitpack(S[j1][2], S[j1][3], pah[3], pal[3]);
            const int rowv = 16 * kc2 + (lane & 7) + 8 * ((lane >> 3) & 1);
#pragma unroll
            for (int jd = 0; jd < 8; jd++) {
                uint32_t bvh[2], bvl[2];
                uint32_t sw = swz128(rowv, jd);
                LDSM2T(bvh, stg + CTX_OFF_VH + sw);
                LDSM2T(bvl, stg + CTX_OFF_VL + sw);
                MMA16816(O[jd], pah, bvh);
                MMA16816(O[jd], pal, bvh);
                MMA16816(O[jd], pah, bvl);
            }
        }
        __syncthreads();
    }

    // epilogue: normalize + write ctx (f32, [t*BSZ+b][EMB]) and m/l
    const float li0 = 1.f / l0, li1 = 1.f / l1;
    const int r = lane >> 2;
    const int t0 = q0 + wq0 + r, t1 = t0 + 8;
    float* o0 = g_ctx + ((size_t)t0 * BSZ + b) * EMB + hh * HD;
    float* o1 = g_ctx + ((size_t)t1 * BSZ + b) * EMB + hh * HD;
#pragma unroll
    for (int jd = 0; jd < 8; jd++) {
        *(float2*)&o0[8 * jd + cc] = make_float2(O[jd][0] * li0, O[jd][1] * li0);
        *(float2*)&o1[8 * jd + cc] = make_float2(O[jd][2] * li1, O[jd][3] * li1);
    }
    if ((lane & 3) == 0) {
        g_m[bh * T_LEN + t0] = m0;  g_m[bh * T_LEN + t1] = m1;
        g_l[bh * T_LEN + t0] = l0;  g_l[bh * T_LEN + t1] = l1;
    }
}

// ---------------- tensor-core avg weights: mean_h softmax(S) ----------------
// CTA: 128 q x 64 k output tile, loops 20 heads; Q/K stages double-buffered.
#define AVG_OFF_QH 0
#define AVG_OFF_QL 16384
#define AVG_OFF_KH 32768
#define AVG_OFF_KL 40960
#define AVG_STAGE 49152
#define AVG_SMEM (2 * AVG_STAGE)   /* 98304 */

__global__ void __launch_bounds__(256, 1)
attn_avgw_mma(float* __restrict__ outAvg)
{
    extern __shared__ char smem[];
    const uint32_t sb = smem_u32(smem);
    const int tid = threadIdx.x, w = tid >> 5, lane = tid & 31;
    const int wq0 = w * 16;
    const int k0 = blockIdx.x * 64, q0 = blockIdx.y * 128, b = blockIdx.z;

    auto copy_stage = [&](int s, int head) {
        const int bh = b * NH + head;
        const __nv_bfloat16* Qh = g_qhi + ((size_t)bh * T_LEN + q0) * HD;
        const __nv_bfloat16* Ql = g_qlo + ((size_t)bh * T_LEN + q0) * HD;
        const __nv_bfloat16* Kh = g_khi + ((size_t)bh * T_LEN + k0) * HD;
        const __nv_bfloat16* Kl = g_klo + ((size_t)bh * T_LEN + k0) * HD;
        const uint32_t stg = sb + s * AVG_STAGE;
#pragma unroll
        for (int i = 0; i < 4; i++) {
            int e = tid + i * 256;
            int row = e >> 3, c = e & 7;
            uint32_t sw = swz128(row, c);
            size_t g = (size_t)row * HD + c * 8;
            CP_ASYNC16(stg + AVG_OFF_QH + sw, Qh + g);
            CP_ASYNC16(stg + AVG_OFF_QL + sw, Ql + g);
        }
#pragma unroll
        for (int i = 0; i < 2; i++) {
            int e = tid + i * 256;
            int row = e >> 3, c = e & 7;
            uint32_t sw = swz128(row, c);
            size_t g = (size_t)row * HD + c * 8;
            CP_ASYNC16(stg + AVG_OFF_KH + sw, Kh + g);
            CP_ASYNC16(stg + AVG_OFF_KL + sw, Kl + g);
        }
    };

    copy_stage(0, 0);
    CP_COMMIT();

    const int r = lane >> 2, cc = (lane & 3) * 2;
    float2 mv[8];
#pragma unroll
    for (int j = 0; j < 8; j++)
        mv[j] = *(const float2*)&g_maskf[b * T_LEN + k0 + 8 * j + cc];

    float avg[8][4];
#pragma unroll
    for (int j = 0; j < 8; j++)
#pragma unroll
        for (int x = 0; x < 4; x++) avg[j][x] = 0.f;

    for (int head = 0; head < NH; head++) {
        const int cur = head & 1;
        if (head + 1 < NH) { copy_stage(cur ^ 1, head + 1); CP_COMMIT(); CP_WAIT(1); }
        else CP_WAIT(0);
        __syncthreads();
        const uint32_t stg = sb + cur * AVG_STAGE;

        uint32_t qfh[4][4], qfl[4][4];
#pragma unroll
        for (int kc = 0; kc < 4; kc++) {
            int row = wq0 + (lane & 15), c = 2 * kc + (lane >> 4);
            LDSM4(qfh[kc], stg + AVG_OFF_QH + swz128(row, c));
            LDSM4(qfl[kc], stg + AVG_OFF_QL + swz128(row, c));
        }

        float S[8][4];
#pragma unroll
        for (int j = 0; j < 8; j++)
#pragma unroll
            for (int x = 0; x < 4; x++) S[j][x] = 0.f;

#pragma unroll
        for (int kc = 0; kc < 4; kc++) {
#pragma unroll
            for (int j = 0; j < 8; j++) {
                uint32_t kfh[2], kfl[2];
                int rowk = 8 * j + (lane & 7), ck = 2 * kc + ((lane >> 3) & 1);
                uint32_t sw = swz128(rowk, ck);
                LDSM2(kfh, stg + AVG_OFF_KH + sw);
                LDSM2(kfl, stg + AVG_OFF_KL + sw);
                MMA16816(S[j], qfh[kc], kfh);
                MMA16816(S[j], qfl[kc], kfh);
                MMA16816(S[j], qfh[kc], kfl);
            }
        }

        const int bh = b * NH + head;
        const float mq0 = g_m[bh * T_LEN + q0 + wq0 + r];
        const float mq1 = g_m[bh * T_LEN + q0 + wq0 + r + 8];
        const float li0 = 1.f / g_l[bh * T_LEN + q0 + wq0 + r];
        const float li1 = 1.f / g_l[bh * T_LEN + q0 + wq0 + r + 8];
#pragma unroll
        for (int j = 0; j < 8; j++) {
            avg[j][0] += __expf(S[j][0] + mv[j].x - mq0) * li0;
            avg[j][1] += __expf(S[j][1] + mv[j].y - mq0) * li0;
            avg[j][2] += __expf(S[j][2] + mv[j].x - mq1) * li1;
            avg[j][3] += __expf(S[j][3] + mv[j].y - mq1) * li1;
        }
        __syncthreads();
    }

    const float invH = 1.0f / NH;
    const int t0 = q0 + wq0 + r, t1 = t0 + 8;
    float* o0 = outAvg + ((size_t)b * T_LEN + t0) * T_LEN + k0;
    float* o1 = outAvg + ((size_t)b * T_LEN + t1) * T_LEN + k0;
#pragma unroll
    for (int j = 0; j < 8; j++) {
        *(float2*)&o0[8 * j + cc] = make_float2(avg[j][0] * invH, avg[j][1] * invH);
        *(float2*)&o1[8 * j + cc] = make_float2(avg[j][2] * invH, avg[j][3] * invH);
    }
}

// ---------------- launch ----------------
extern "C" void kernel_launch(void* const* d_in, const int* in_sizes, int n_in,
                              void* d_out, int out_size)
{
    const float* query = (const float*)d_in[0];
    const void*  maskp = d_in[1];
    const float* Wq = (const float*)d_in[2];
    const float* bq = (const float*)d_in[3];
    const float* Wk = (const float*)d_in[4];
    const float* bk = (const float*)d_in[5];
    const float* Wv = (const float*)d_in[6];
    const float* bv = (const float*)d_in[7];
    const float* Wo = (const float*)d_in[8];
    const float* bo = (const float*)d_in[9];
    float* outAttn = (float*)d_out;
    float* outAvg  = outAttn + (size_t)MROWS * EMB;

    float* ctxp;
    __nv_bfloat16 *ahi, *alo, *wthi, *wtlo;
    __nv_bfloat16 *qhi, *qlo, *khi, *klo, *vhi, *vlo;
    cudaGetSymbolAddress((void**)&ctxp, g_ctx);
    cudaGetSymbolAddress((void**)&ahi, g_ahi);
    cudaGetSymbolAddress((void**)&alo, g_alo);
    cudaGetSymbolAddress((void**)&wthi, g_wthi);
    cudaGetSymbolAddress((void**)&wtlo, g_wtlo);
    cudaGetSymbolAddress((void**)&qhi, g_qhi);
    cudaGetSymbolAddress((void**)&qlo, g_qlo);
    cudaGetSymbolAddress((void**)&khi, g_khi);
    cudaGetSymbolAddress((void**)&klo, g_klo);
    cudaGetSymbolAddress((void**)&vhi, g_vhi);
    cudaGetSymbolAddress((void**)&vlo, g_vlo);

    maskf_build_kernel<<<1, 256>>>((const unsigned char*)maskp);

    const int n4 = MROWS * EMB / 4;
    cvt_split_kernel<<<(n4 + 255) / 256, 256>>>(query, ahi, alo, n4);
    const size_t WSZ = (size_t)EMB * EMB;
    dim3 tg(EMB / 32, EMB / 32), tb(32, 8);
    tsp_split_kernel<<<tg, tb>>>(Wq, wthi + 0 * WSZ, wtlo + 0 * WSZ);
    tsp_split_kernel<<<tg, tb>>>(Wk, wthi + 1 * WSZ, wtlo + 1 * WSZ);
    tsp_split_kernel<<<tg, tb>>>(Wv, wthi + 2 * WSZ, wtlo + 2 * WSZ);
    tsp_split_kernel<<<tg, tb>>>(Wo, wthi + 3 * WSZ, wtlo + 3 * WSZ);

    cudaFuncSetAttribute(tc_gemm_kernel<0>, cudaFuncAttributeMaxDynamicSharedMemorySize, GEMM_SMEM);
    cudaFuncSetAttribute(tc_gemm_kernel<1>, cudaFuncAttributeMaxDynamicSharedMemorySize, GEMM_SMEM);
    cudaFuncSetAttribute(attn_ctx_mma, cudaFuncAttributeMaxDynamicSharedMemorySize, CTX_SMEM);
    cudaFuncSetAttribute(attn_avgw_mma, cudaFuncAttributeMaxDynamicSharedMemorySize, AVG_SMEM);

    dim3 gg(MROWS / BM, EMB / BN);
    tc_gemm_kernel<1><<<gg, 256, GEMM_SMEM>>>(ahi, alo, wthi + 0 * WSZ, wtlo + 0 * WSZ, bq,
                                              nullptr, qhi, qlo, SCALING);
    tc_gemm_kernel<1><<<gg, 256, GEMM_SMEM>>>(ahi, alo, wthi + 1 * WSZ, wtlo + 1 * WSZ, bk,
                                              nullptr, khi, klo, 1.0f);
    tc_gemm_kernel<1><<<gg, 256, GEMM_SMEM>>>(ahi, alo, wthi + 2 * WSZ, wtlo + 2 * WSZ, bv,
                                              nullptr, vhi, vlo, 1.0f);

    attn_ctx_mma<<<dim3(T_LEN / 128, BHEADS), 256, CTX_SMEM>>>();

    cvt_split_kernel<<<(n4 + 255) / 256, 256>>>(ctxp, ahi, alo, n4);
    tc_gemm_kernel<0><<<gg, 256, GEMM_SMEM>>>(ahi, alo, wthi + 3 * WSZ, wtlo + 3 * WSZ, bo,
                                              outAttn, nullptr, nullptr, 1.0f);

    attn_avgw_mma<<<dim3(T_LEN / 64, T_LEN / 128, BSZ), 256, AVG_SMEM>>>(outAvg);
}